// round 12
// baseline (speedup 1.0000x reference)
#include <cuda_runtime.h>
#include <cuda_fp16.h>

#define NN 50000
#define NE 800000
#define FIN 16
#define FE 8
#define HD 8
#define NG 512

// Persistent-kernel geometry: 148 SMs x 4 blocks, co-residency guaranteed by
// __launch_bounds__(256,4) (<=64 regs) + ~7KB static smem (<<228KB/SM).
#define NBLK 592
#define NTHR (NBLK * 256)

// Scratch (allocation-free: __device__ globals).
// g_Yh:  per-node factor table fp16 [n][o][a]: row = 128B = 1 line; lane r's
//        uint4 at n*128+r*16 covers o=r fully (in-lane dot).
// g_base: per-node base term base[n][o], fp32.
// g_agg:  scatter accumulators fp32, [layer][n*8+o].
__device__ __half2 g_Yh[NN * 32];
__device__ float   g_base[NN * HD];
__device__ float   g_agg[2][NN * HD];

// Grid barrier state. g_count returns to 0 after each barrier; g_gen only
// ever increments (equality-tested) -> safe across graph replays.
__device__ unsigned g_count = 0;
__device__ unsigned g_gen   = 0;

__device__ __forceinline__ void gbar() {
    __syncthreads();
    if (threadIdx.x == 0) {
        unsigned gen = atomicAdd(&g_gen, 0u);      // read gen BEFORE arriving
        __threadfence();                           // publish phase writes
        if (atomicAdd(&g_count, 1u) == NBLK - 1) {
            atomicExch(&g_count, 0u);
            __threadfence();
            atomicAdd(&g_gen, 1u);                 // release
        } else {
            while (atomicAdd(&g_gen, 0u) == gen) {}
        }
        __threadfence();                           // acquire
    }
    __syncthreads();
}

__global__ void __launch_bounds__(256, 4)
k_fused(const float* __restrict__ x, const int* __restrict__ ei,
        const float* __restrict__ ea, const int* __restrict__ batch,
        const float* __restrict__ We1, const float* __restrict__ be1,
        const float* __restrict__ root1, const float* __restrict__ b1,
        const float* __restrict__ We2, const float* __restrict__ be2,
        const float* __restrict__ root2, const float* __restrict__ b2,
        const float* __restrict__ Wlast, const float* __restrict__ blast,
        float* __restrict__ out) {
    // ---- one-time smem staging of ALL weights (both layers) ----
    __shared__ float sW1[FIN * HD * HD];   // [i][o][a]
    __shared__ float sWc1[FIN * HD];       // root1 + be1 : [i][o]
    __shared__ float sW2[HD * HD * HD];    // [i][o][a]
    __shared__ float sWc2[HD * HD];        // root2 + be2 : [i][o]
    for (int t = threadIdx.x; t < FIN * 64; t += 256) {
        int i = t >> 6, o = (t >> 3) & 7, a = t & 7;
        sW1[t] = We1[a * (FIN * HD) + i * HD + o];
    }
    for (int t = threadIdx.x; t < FIN * HD; t += 256)
        sWc1[t] = root1[t] + be1[t];
    for (int t = threadIdx.x; t < HD * 64; t += 256) {
        int i = t >> 6, o = (t >> 3) & 7, a = t & 7;
        sW2[t] = We2[a * (HD * HD) + i * HD + o];
    }
    for (int t = threadIdx.x; t < HD * HD; t += 256)
        sWc2[t] = root2[t] + be2[t];
    __syncthreads();

    const int tid0 = blockIdx.x * 256 + threadIdx.x;
    const int lane = threadIdx.x & 31;
    const unsigned FULL = 0xffffffffu;
    const float4* sW4_1 = (const float4*)sW1;
    const float4* sW4_2 = (const float4*)sW2;

    // ================= Phase A: node1 + init =================
    // out seed, zero both agg layers
    for (int t = tid0; t < NN * 2; t += NTHR) {
        ((float4*)g_agg[0])[t] = make_float4(0.f, 0.f, 0.f, 0.f);
        ((float4*)g_agg[1])[t] = make_float4(0.f, 0.f, 0.f, 0.f);
    }
    if (tid0 < NG) out[tid0] = blast[0];

    for (int t = tid0; t < NN * HD; t += NTHR) {
        int n = t >> 3, o = t & 7;
        float xv[FIN];
        const float4* xp = (const float4*)(x + n * FIN);
        #pragma unroll
        for (int q = 0; q < 4; q++) {
            float4 v = xp[q];
            xv[q * 4 + 0] = v.x; xv[q * 4 + 1] = v.y;
            xv[q * 4 + 2] = v.z; xv[q * 4 + 3] = v.w;
        }
        float4 acc0 = make_float4(0.f, 0.f, 0.f, 0.f);
        float4 acc1 = make_float4(0.f, 0.f, 0.f, 0.f);
        float bacc = __ldg(b1 + o);
        #pragma unroll
        for (int i = 0; i < FIN; i++) {
            float xi = xv[i];
            float4 w0 = sW4_1[(i * HD + o) * 2 + 0];
            float4 w1 = sW4_1[(i * HD + o) * 2 + 1];
            acc0.x = fmaf(xi, w0.x, acc0.x); acc0.y = fmaf(xi, w0.y, acc0.y);
            acc0.z = fmaf(xi, w0.z, acc0.z); acc0.w = fmaf(xi, w0.w, acc0.w);
            acc1.x = fmaf(xi, w1.x, acc1.x); acc1.y = fmaf(xi, w1.y, acc1.y);
            acc1.z = fmaf(xi, w1.z, acc1.z); acc1.w = fmaf(xi, w1.w, acc1.w);
            bacc = fmaf(xi, sWc1[i * HD + o], bacc);
        }
        __half2 hy[4];
        hy[0] = __floats2half2_rn(acc0.x, acc0.y);
        hy[1] = __floats2half2_rn(acc0.z, acc0.w);
        hy[2] = __floats2half2_rn(acc1.x, acc1.y);
        hy[3] = __floats2half2_rn(acc1.z, acc1.w);
        *(uint4*)(g_Yh + n * 32 + o * 4) = *(const uint4*)hy;
        g_base[t] = bacc;
    }
    gbar();

    // ================= edge phase (both layers) =================
    // 8 lanes/edge, 4 edges/task (e, e+Q, e+2Q, e+3Q); grid-stride NTHR is
    // divisible by 8 so lane-group alignment is loop-invariant.
    #define EDGE_PHASE(AGG)                                                     \
    {                                                                           \
        const int Q = NE / 4;                                                   \
        float* aggL = (AGG);                                                    \
        for (int t = tid0; t < (NE / 4) * 8; t += NTHR) {                       \
            int r = t & 7;                                                      \
            int q = t >> 3;                                                     \
            int e0 = q, e1 = q + Q, e2 = q + 2 * Q, e3 = q + 3 * Q;             \
            int src0 = __ldg(ei + e0);                                          \
            int src1 = __ldg(ei + e1);                                          \
            int src2 = __ldg(ei + e2);                                          \
            int src3 = __ldg(ei + e3);                                          \
            int dst0 = __ldg(ei + NE + e0);                                     \
            int dst1 = __ldg(ei + NE + e1);                                     \
            int dst2 = __ldg(ei + NE + e2);                                     \
            int dst3 = __ldg(ei + NE + e3);                                     \
            float4 a00 = __ldg((const float4*)(ea + e0 * FE));                  \
            float4 a01 = __ldg((const float4*)(ea + e0 * FE + 4));              \
            float4 a10 = __ldg((const float4*)(ea + e1 * FE));                  \
            float4 a11 = __ldg((const float4*)(ea + e1 * FE + 4));              \
            float4 a20 = __ldg((const float4*)(ea + e2 * FE));                  \
            float4 a21 = __ldg((const float4*)(ea + e2 * FE + 4));              \
            float4 a30 = __ldg((const float4*)(ea + e3 * FE));                  \
            float4 a31 = __ldg((const float4*)(ea + e3 * FE + 4));              \
            uint4 yq0 = __ldg((const uint4*)(g_Yh + src0 * 32 + r * 4));        \
            uint4 yq1 = __ldg((const uint4*)(g_Yh + src1 * 32 + r * 4));        \
            uint4 yq2 = __ldg((const uint4*)(g_Yh + src2 * 32 + r * 4));        \
            uint4 yq3 = __ldg((const uint4*)(g_Yh + src3 * 32 + r * 4));        \
            EDGE_EMIT(yq0, a00, a01, dst0)                                      \
            EDGE_EMIT(yq1, a10, a11, dst1)                                      \
            EDGE_EMIT(yq2, a20, a21, dst2)                                      \
            EDGE_EMIT(yq3, a30, a31, dst3)                                      \
        }                                                                       \
    }

    #define EDGE_EMIT(yq, A0, A1, dst)                                          \
    {                                                                           \
        const __half2* yh = (const __half2*)&(yq);                              \
        __half2 eh0 = __floats2half2_rn((A0).x, (A0).y);                        \
        __half2 eh1 = __floats2half2_rn((A0).z, (A0).w);                        \
        __half2 eh2 = __floats2half2_rn((A1).x, (A1).y);                        \
        __half2 eh3 = __floats2half2_rn((A1).z, (A1).w);                        \
        __half2 hac = __hmul2(eh0, yh[0]);                                      \
        hac = __hfma2(eh1, yh[1], hac);                                         \
        hac = __hfma2(eh2, yh[2], hac);                                         \
        hac = __hfma2(eh3, yh[3], hac);                                         \
        float2 fa = __half22float2(hac);                                        \
        float m = fa.x + fa.y;                                                  \
        float ma = __shfl_sync(FULL, m, (lane + 1) & 31);                       \
        float mb = __shfl_sync(FULL, m, (lane + 2) & 31);                       \
        float mc = __shfl_sync(FULL, m, (lane + 3) & 31);                       \
        if ((r & 3) == 0) {                                                     \
            float* p = aggL + (dst) * HD + r;                                   \
            asm volatile("red.global.add.v4.f32 [%0], {%1, %2, %3, %4};"        \
                         :: "l"(p), "f"(m), "f"(ma), "f"(mb), "f"(mc)           \
                         : "memory");                                           \
        }                                                                       \
    }

    // ================= Phase B: edge layer 0 =================
    EDGE_PHASE(g_agg[0])
    gbar();

    // ================= Phase C: node2 =================
    for (int t = tid0; t < NN * HD; t += NTHR) {
        int n = t >> 3, o = t & 7;
        float h[HD];
        {
            const float4* ap = (const float4*)(g_agg[0] + n * HD);
            const float4* cp = (const float4*)(g_base + n * HD);
            float4 a0 = ap[0], a1 = ap[1], c0 = cp[0], c1 = cp[1];
            h[0] = fmaxf(a0.x + c0.x, 0.f); h[1] = fmaxf(a0.y + c0.y, 0.f);
            h[2] = fmaxf(a0.z + c0.z, 0.f); h[3] = fmaxf(a0.w + c0.w, 0.f);
            h[4] = fmaxf(a1.x + c1.x, 0.f); h[5] = fmaxf(a1.y + c1.y, 0.f);
            h[6] = fmaxf(a1.z + c1.z, 0.f); h[7] = fmaxf(a1.w + c1.w, 0.f);
        }
        __syncwarp();   // lanes of node n read base before warp-mates overwrite

        float4 acc0 = make_float4(0.f, 0.f, 0.f, 0.f);
        float4 acc1 = make_float4(0.f, 0.f, 0.f, 0.f);
        float bacc = __ldg(b2 + o);
        #pragma unroll
        for (int i = 0; i < HD; i++) {
            float hi = h[i];
            float4 w0 = sW4_2[(i * HD + o) * 2 + 0];
            float4 w1 = sW4_2[(i * HD + o) * 2 + 1];
            acc0.x = fmaf(hi, w0.x, acc0.x); acc0.y = fmaf(hi, w0.y, acc0.y);
            acc0.z = fmaf(hi, w0.z, acc0.z); acc0.w = fmaf(hi, w0.w, acc0.w);
            acc1.x = fmaf(hi, w1.x, acc1.x); acc1.y = fmaf(hi, w1.y, acc1.y);
            acc1.z = fmaf(hi, w1.z, acc1.z); acc1.w = fmaf(hi, w1.w, acc1.w);
            bacc = fmaf(hi, sWc2[i * HD + o], bacc);
        }
        __half2 hy[4];
        hy[0] = __floats2half2_rn(acc0.x, acc0.y);
        hy[1] = __floats2half2_rn(acc0.z, acc0.w);
        hy[2] = __floats2half2_rn(acc1.x, acc1.y);
        hy[3] = __floats2half2_rn(acc1.z, acc1.w);
        *(uint4*)(g_Yh + n * 32 + o * 4) = *(const uint4*)hy;
        g_base[t] = bacc;
    }
    gbar();

    // ================= Phase D: edge layer 1 =================
    EDGE_PHASE(g_agg[1])
    #undef EDGE_EMIT
    #undef EDGE_PHASE
    gbar();

    // ================= Phase E: pool =================
    // batch SORTED -> warp-segmented reduction; all warp lanes execute the
    // shuffles uniformly (guards only zero the contribution).
    {
        int n = tid0;
        int bid = -1;
        float s = 0.f;
        if (n < NN) {
            bid = __ldg(batch + n);
            const float4* ap = (const float4*)(g_agg[1] + n * HD);
            const float4* cp = (const float4*)(g_base + n * HD);
            float4 a0 = ap[0], a1 = ap[1], c0 = cp[0], c1 = cp[1];
            s = fmaxf(a0.x + c0.x, 0.f) * __ldg(Wlast + 0)
              + fmaxf(a0.y + c0.y, 0.f) * __ldg(Wlast + 1)
              + fmaxf(a0.z + c0.z, 0.f) * __ldg(Wlast + 2)
              + fmaxf(a0.w + c0.w, 0.f) * __ldg(Wlast + 3)
              + fmaxf(a1.x + c1.x, 0.f) * __ldg(Wlast + 4)
              + fmaxf(a1.y + c1.y, 0.f) * __ldg(Wlast + 5)
              + fmaxf(a1.z + c1.z, 0.f) * __ldg(Wlast + 6)
              + fmaxf(a1.w + c1.w, 0.f) * __ldg(Wlast + 7);
        }
        int bprev = __shfl_up_sync(FULL, bid, 1);
        #pragma unroll
        for (int d = 1; d < 32; d <<= 1) {
            float tv = __shfl_down_sync(FULL, s, d);
            int  tb = __shfl_down_sync(FULL, bid, d);
            if (lane + d < 32 && tb == bid) s += tv;
        }
        bool leader = (n < NN) && (lane == 0 || bprev != bid);
        if (leader) atomicAdd(out + bid, s);
    }
}

extern "C" void kernel_launch(void* const* d_in, const int* in_sizes, int n_in,
                              void* d_out, int out_size) {
    const float* x     = (const float*)d_in[0];
    const int*   ei    = (const int*)  d_in[1];
    const float* ea    = (const float*)d_in[2];
    const int*   batch = (const int*)  d_in[3];
    const float* We1   = (const float*)d_in[4];
    const float* be1   = (const float*)d_in[5];
    const float* root1 = (const float*)d_in[6];
    const float* b1    = (const float*)d_in[7];
    const float* We2   = (const float*)d_in[8];
    const float* be2   = (const float*)d_in[9];
    const float* root2 = (const float*)d_in[10];
    const float* b2    = (const float*)d_in[11];
    const float* Wlast = (const float*)d_in[12];
    const float* blast = (const float*)d_in[13];
    float* out = (float*)d_out;

    k_fused<<<NBLK, 256>>>(x, ei, ea, batch, We1, be1, root1, b1,
                           We2, be2, root2, b2, Wlast, blast, out);
}

// round 14
// speedup vs baseline: 1.0062x; 1.0062x over previous
#include <cuda_runtime.h>
#include <cuda_fp16.h>

#define NN 50000
#define NE 800000
#define FIN 16
#define FE 8
#define HD 8
#define NG 512

// Persistent-kernel geometry: 148 SMs x 4 blocks (GB300 has 152 SMs -> 608
// resident slots, so all 592 blocks are co-resident; guaranteed by
// __launch_bounds__(256,4): <=64 regs, ~7KB static smem << 228KB/SM).
#define NBLK 592
#define NTHR (NBLK * 256)

// Scratch (allocation-free: __device__ globals).
__device__ __half2 g_Yh[NN * 32];     // fp16 Y[n][o][a], 128B row = 1 line
__device__ float   g_base[NN * HD];   // fp32 base[n][o]
__device__ float   g_agg[2][NN * HD]; // fp32 scatter accumulators

// Grid barrier state. g_count returns to 0 after each barrier; g_gen only
// ever increments (equality-tested) -> safe across graph replays.
__device__ unsigned g_count = 0;
__device__ unsigned g_gen   = 0;

__device__ __forceinline__ unsigned ld_vol(unsigned* p) {
    unsigned v;
    asm volatile("ld.volatile.global.u32 %0, [%1];" : "=r"(v) : "l"(p));
    return v;
}

// Sense-reversing grid barrier. Pollers use volatile LOADS (hot-line reads
// are served at sector rate — no per-address RMW serialization like an
// atomic poll) + nanosleep backoff. Only the release is an atomic.
__device__ __forceinline__ void gbar() {
    __syncthreads();
    if (threadIdx.x == 0) {
        unsigned gen = ld_vol(&g_gen);             // read gen BEFORE arriving
        __threadfence();                           // publish phase writes
        if (atomicAdd(&g_count, 1u) == NBLK - 1) {
            atomicExch(&g_count, 0u);
            __threadfence();
            atomicAdd(&g_gen, 1u);                 // release
        } else {
            while (ld_vol(&g_gen) == gen) __nanosleep(128);
        }
        __threadfence();                           // acquire
    }
    __syncthreads();
}

__global__ void __launch_bounds__(256, 4)
k_fused(const float* __restrict__ x, const int* __restrict__ ei,
        const float* __restrict__ ea, const int* __restrict__ batch,
        const float* __restrict__ We1, const float* __restrict__ be1,
        const float* __restrict__ root1, const float* __restrict__ b1,
        const float* __restrict__ We2, const float* __restrict__ be2,
        const float* __restrict__ root2, const float* __restrict__ b2,
        const float* __restrict__ Wlast, const float* __restrict__ blast,
        float* __restrict__ out) {
    // ---- one-time smem staging of ALL weights (both layers) ----
    __shared__ float sW1[FIN * HD * HD];   // [i][o][a]
    __shared__ float sWc1[FIN * HD];       // root1 + be1 : [i][o]
    __shared__ float sW2[HD * HD * HD];    // [i][o][a]
    __shared__ float sWc2[HD * HD];        // root2 + be2 : [i][o]
    for (int t = threadIdx.x; t < FIN * 64; t += 256) {
        int i = t >> 6, o = (t >> 3) & 7, a = t & 7;
        sW1[t] = We1[a * (FIN * HD) + i * HD + o];
    }
    for (int t = threadIdx.x; t < FIN * HD; t += 256)
        sWc1[t] = root1[t] + be1[t];
    for (int t = threadIdx.x; t < HD * 64; t += 256) {
        int i = t >> 6, o = (t >> 3) & 7, a = t & 7;
        sW2[t] = We2[a * (HD * HD) + i * HD + o];
    }
    for (int t = threadIdx.x; t < HD * HD; t += 256)
        sWc2[t] = root2[t] + be2[t];
    __syncthreads();

    const int tid0 = blockIdx.x * 256 + threadIdx.x;
    const int lane = threadIdx.x & 31;
    const unsigned FULL = 0xffffffffu;
    const float4* sW4_1 = (const float4*)sW1;
    const float4* sW4_2 = (const float4*)sW2;

    // ================= Phase A: node1 + init =================
    for (int t = tid0; t < NN * 2; t += NTHR) {
        ((float4*)g_agg[0])[t] = make_float4(0.f, 0.f, 0.f, 0.f);
        ((float4*)g_agg[1])[t] = make_float4(0.f, 0.f, 0.f, 0.f);
    }
    if (tid0 < NG) out[tid0] = blast[0];

    for (int t = tid0; t < NN * HD; t += NTHR) {
        int n = t >> 3, o = t & 7;
        float xv[FIN];
        const float4* xp = (const float4*)(x + n * FIN);
        #pragma unroll
        for (int q = 0; q < 4; q++) {
            float4 v = xp[q];
            xv[q * 4 + 0] = v.x; xv[q * 4 + 1] = v.y;
            xv[q * 4 + 2] = v.z; xv[q * 4 + 3] = v.w;
        }
        float4 acc0 = make_float4(0.f, 0.f, 0.f, 0.f);
        float4 acc1 = make_float4(0.f, 0.f, 0.f, 0.f);
        float bacc = __ldg(b1 + o);
        #pragma unroll
        for (int i = 0; i < FIN; i++) {
            float xi = xv[i];
            float4 w0 = sW4_1[(i * HD + o) * 2 + 0];
            float4 w1 = sW4_1[(i * HD + o) * 2 + 1];
            acc0.x = fmaf(xi, w0.x, acc0.x); acc0.y = fmaf(xi, w0.y, acc0.y);
            acc0.z = fmaf(xi, w0.z, acc0.z); acc0.w = fmaf(xi, w0.w, acc0.w);
            acc1.x = fmaf(xi, w1.x, acc1.x); acc1.y = fmaf(xi, w1.y, acc1.y);
            acc1.z = fmaf(xi, w1.z, acc1.z); acc1.w = fmaf(xi, w1.w, acc1.w);
            bacc = fmaf(xi, sWc1[i * HD + o], bacc);
        }
        __half2 hy[4];
        hy[0] = __floats2half2_rn(acc0.x, acc0.y);
        hy[1] = __floats2half2_rn(acc0.z, acc0.w);
        hy[2] = __floats2half2_rn(acc1.x, acc1.y);
        hy[3] = __floats2half2_rn(acc1.z, acc1.w);
        *(uint4*)(g_Yh + n * 32 + o * 4) = *(const uint4*)hy;
        g_base[t] = bacc;
    }
    gbar();

    // ================= edge phases =================
    #define EDGE_EMIT(yq, A0, A1, dst)                                          \
    {                                                                           \
        const __half2* yh = (const __half2*)&(yq);                              \
        __half2 eh0 = __floats2half2_rn((A0).x, (A0).y);                        \
        __half2 eh1 = __floats2half2_rn((A0).z, (A0).w);                        \
        __half2 eh2 = __floats2half2_rn((A1).x, (A1).y);                        \
        __half2 eh3 = __floats2half2_rn((A1).z, (A1).w);                        \
        __half2 hac = __hmul2(eh0, yh[0]);                                      \
        hac = __hfma2(eh1, yh[1], hac);                                         \
        hac = __hfma2(eh2, yh[2], hac);                                         \
        hac = __hfma2(eh3, yh[3], hac);                                         \
        float2 fa = __half22float2(hac);                                        \
        float m = fa.x + fa.y;                                                  \
        float ma = __shfl_sync(FULL, m, (lane + 1) & 31);                       \
        float mb = __shfl_sync(FULL, m, (lane + 2) & 31);                       \
        float mc = __shfl_sync(FULL, m, (lane + 3) & 31);                       \
        if ((r & 3) == 0) {                                                     \
            float* p = aggL + (dst) * HD + r;                                   \
            asm volatile("red.global.add.v4.f32 [%0], {%1, %2, %3, %4};"        \
                         :: "l"(p), "f"(m), "f"(ma), "f"(mb), "f"(mc)           \
                         : "memory");                                           \
        }                                                                       \
    }

    #define EDGE_PHASE(AGG)                                                     \
    {                                                                           \
        const int Q = NE / 4;                                                   \
        float* aggL = (AGG);                                                    \
        for (int t = tid0; t < (NE / 4) * 8; t += NTHR) {                       \
            int r = t & 7;                                                      \
            int q = t >> 3;                                                     \
            int e0 = q, e1 = q + Q, e2 = q + 2 * Q, e3 = q + 3 * Q;             \
            int src0 = __ldg(ei + e0);                                          \
            int src1 = __ldg(ei + e1);                                          \
            int src2 = __ldg(ei + e2);                                          \
            int src3 = __ldg(ei + e3);                                          \
            int dst0 = __ldg(ei + NE + e0);                                     \
            int dst1 = __ldg(ei + NE + e1);                                     \
            int dst2 = __ldg(ei + NE + e2);                                     \
            int dst3 = __ldg(ei + NE + e3);                                     \
            float4 a00 = __ldg((const float4*)(ea + e0 * FE));                  \
            float4 a01 = __ldg((const float4*)(ea + e0 * FE + 4));              \
            float4 a10 = __ldg((const float4*)(ea + e1 * FE));                  \
            float4 a11 = __ldg((const float4*)(ea + e1 * FE + 4));              \
            float4 a20 = __ldg((const float4*)(ea + e2 * FE));                  \
            float4 a21 = __ldg((const float4*)(ea + e2 * FE + 4));              \
            float4 a30 = __ldg((const float4*)(ea + e3 * FE));                  \
            float4 a31 = __ldg((const float4*)(ea + e3 * FE + 4));              \
            uint4 yq0 = __ldg((const uint4*)(g_Yh + src0 * 32 + r * 4));        \
            uint4 yq1 = __ldg((const uint4*)(g_Yh + src1 * 32 + r * 4));        \
            uint4 yq2 = __ldg((const uint4*)(g_Yh + src2 * 32 + r * 4));        \
            uint4 yq3 = __ldg((const uint4*)(g_Yh + src3 * 32 + r * 4));        \
            EDGE_EMIT(yq0, a00, a01, dst0)                                      \
            EDGE_EMIT(yq1, a10, a11, dst1)                                      \
            EDGE_EMIT(yq2, a20, a21, dst2)                                      \
            EDGE_EMIT(yq3, a30, a31, dst3)                                      \
        }                                                                       \
    }

    // ================= Phase B: edge layer 0 =================
    EDGE_PHASE(g_agg[0])
    gbar();

    // ================= Phase C: node2 =================
    for (int t = tid0; t < NN * HD; t += NTHR) {
        int n = t >> 3, o = t & 7;
        float h[HD];
        {
            const float4* ap = (const float4*)(g_agg[0] + n * HD);
            const float4* cp = (const float4*)(g_base + n * HD);
            float4 a0 = ap[0], a1 = ap[1], c0 = cp[0], c1 = cp[1];
            h[0] = fmaxf(a0.x + c0.x, 0.f); h[1] = fmaxf(a0.y + c0.y, 0.f);
            h[2] = fmaxf(a0.z + c0.z, 0.f); h[3] = fmaxf(a0.w + c0.w, 0.f);
            h[4] = fmaxf(a1.x + c1.x, 0.f); h[5] = fmaxf(a1.y + c1.y, 0.f);
            h[6] = fmaxf(a1.z + c1.z, 0.f); h[7] = fmaxf(a1.w + c1.w, 0.f);
        }
        __syncwarp();   // lanes of node n read base before warp-mates overwrite

        float4 acc0 = make_float4(0.f, 0.f, 0.f, 0.f);
        float4 acc1 = make_float4(0.f, 0.f, 0.f, 0.f);
        float bacc = __ldg(b2 + o);
        #pragma unroll
        for (int i = 0; i < HD; i++) {
            float hi = h[i];
            float4 w0 = sW4_2[(i * HD + o) * 2 + 0];
            float4 w1 = sW4_2[(i * HD + o) * 2 + 1];
            acc0.x = fmaf(hi, w0.x, acc0.x); acc0.y = fmaf(hi, w0.y, acc0.y);
            acc0.z = fmaf(hi, w0.z, acc0.z); acc0.w = fmaf(hi, w0.w, acc0.w);
            acc1.x = fmaf(hi, w1.x, acc1.x); acc1.y = fmaf(hi, w1.y, acc1.y);
            acc1.z = fmaf(hi, w1.z, acc1.z); acc1.w = fmaf(hi, w1.w, acc1.w);
            bacc = fmaf(hi, sWc2[i * HD + o], bacc);
        }
        __half2 hy[4];
        hy[0] = __floats2half2_rn(acc0.x, acc0.y);
        hy[1] = __floats2half2_rn(acc0.z, acc0.w);
        hy[2] = __floats2half2_rn(acc1.x, acc1.y);
        hy[3] = __floats2half2_rn(acc1.z, acc1.w);
        *(uint4*)(g_Yh + n * 32 + o * 4) = *(const uint4*)hy;
        g_base[t] = bacc;
    }
    gbar();

    // ================= Phase D: edge layer 1 =================
    EDGE_PHASE(g_agg[1])
    #undef EDGE_EMIT
    #undef EDGE_PHASE
    gbar();

    // ================= Phase E: pool =================
    {
        int n = tid0;
        int bid = -1;
        float s = 0.f;
        if (n < NN) {
            bid = __ldg(batch + n);
            const float4* ap = (const float4*)(g_agg[1] + n * HD);
            const float4* cp = (const float4*)(g_base + n * HD);
            float4 a0 = ap[0], a1 = ap[1], c0 = cp[0], c1 = cp[1];
            s = fmaxf(a0.x + c0.x, 0.f) * __ldg(Wlast + 0)
              + fmaxf(a0.y + c0.y, 0.f) * __ldg(Wlast + 1)
              + fmaxf(a0.z + c0.z, 0.f) * __ldg(Wlast + 2)
              + fmaxf(a0.w + c0.w, 0.f) * __ldg(Wlast + 3)
              + fmaxf(a1.x + c1.x, 0.f) * __ldg(Wlast + 4)
              + fmaxf(a1.y + c1.y, 0.f) * __ldg(Wlast + 5)
              + fmaxf(a1.z + c1.z, 0.f) * __ldg(Wlast + 6)
              + fmaxf(a1.w + c1.w, 0.f) * __ldg(Wlast + 7);
        }
        int bprev = __shfl_up_sync(FULL, bid, 1);
        #pragma unroll
        for (int d = 1; d < 32; d <<= 1) {
            float tv = __shfl_down_sync(FULL, s, d);
            int  tb = __shfl_down_sync(FULL, bid, d);
            if (lane + d < 32 && tb == bid) s += tv;
        }
        bool leader = (n < NN) && (lane == 0 || bprev != bid);
        if (leader) atomicAdd(out + bid, s);
    }
}

extern "C" void kernel_launch(void* const* d_in, const int* in_sizes, int n_in,
                              void* d_out, int out_size) {
    const float* x     = (const float*)d_in[0];
    const int*   ei    = (const int*)  d_in[1];
    const float* ea    = (const float*)d_in[2];
    const int*   batch = (const int*)  d_in[3];
    const float* We1   = (const float*)d_in[4];
    const float* be1   = (const float*)d_in[5];
    const float* root1 = (const float*)d_in[6];
    const float* b1    = (const float*)d_in[7];
    const float* We2   = (const float*)d_in[8];
    const float* be2   = (const float*)d_in[9];
    const float* root2 = (const float*)d_in[10];
    const float* b2    = (const float*)d_in[11];
    const float* Wlast = (const float*)d_in[12];
    const float* blast = (const float*)d_in[13];
    float* out = (float*)d_out;

    k_fused<<<NBLK, 256>>>(x, ei, ea, batch, We1, be1, root1, b1,
                           We2, be2, root2, b2, Wlast, blast, out);
}

// round 15
// speedup vs baseline: 1.1290x; 1.1220x over previous
#include <cuda_runtime.h>
#include <cuda_fp16.h>

#define NN 50000
#define NE 800000
#define FIN 16
#define FE 8
#define HD 8
#define NG 512

// Scratch (allocation-free: __device__ globals).
// g_Yh:  per-node factor table fp16 [n][o][a]: row = 128B = 1 line; lane r's
//        uint4 at n*128+r*16 covers o=r fully (in-lane dot).
// g_eah: edge_attr as fp16 (8 halves = 16B per edge), written by edge layer 0
//        as a side product (it already packs ea to half2 for its own dot).
// g_base: per-node base term base[n][o], fp32.
// g_agg:  scatter accumulators fp32, [layer][n*8+o].
__device__ __half2 g_Yh[NN * 32];
__device__ uint4   g_eah[NE];
__device__ float   g_base[NN * HD];
__device__ float   g_agg[2][NN * HD];

// Layer-1 per-node precompute, thread per (n,o). Zeroes agg[0], seeds out.
__global__ void k_node1(const float* __restrict__ x, const float* __restrict__ We1,
                        const float* __restrict__ be1, const float* __restrict__ root1,
                        const float* __restrict__ b1, const float* __restrict__ blast,
                        float* __restrict__ out) {
    __shared__ float sW[FIN * HD * HD];   // [i][o][a]
    __shared__ float sWc[FIN * HD];       // root1 + be1 : [i][o]
    for (int t = threadIdx.x; t < FIN * 64; t += blockDim.x) {
        int i = t >> 6, o = (t >> 3) & 7, a = t & 7;
        sW[t] = We1[a * (FIN * HD) + i * HD + o];
    }
    for (int t = threadIdx.x; t < FIN * HD; t += blockDim.x)
        sWc[t] = root1[t] + be1[t];
    __syncthreads();

    int gid = blockIdx.x * blockDim.x + threadIdx.x;
    if (gid < NG) out[gid] = blast[0];
    if (gid < NN * 2)
        ((float4*)g_agg[0])[gid] = make_float4(0.f, 0.f, 0.f, 0.f);
    int n = gid >> 3, o = gid & 7;
    if (n >= NN) return;

    float xv[FIN];
    const float4* xp = (const float4*)(x + n * FIN);
    #pragma unroll
    for (int q = 0; q < 4; q++) {
        float4 v = xp[q];
        xv[q * 4 + 0] = v.x; xv[q * 4 + 1] = v.y;
        xv[q * 4 + 2] = v.z; xv[q * 4 + 3] = v.w;
    }

    float4 acc0 = make_float4(0.f, 0.f, 0.f, 0.f);   // a = 0..3
    float4 acc1 = make_float4(0.f, 0.f, 0.f, 0.f);   // a = 4..7
    float bacc = __ldg(b1 + o);
    const float4* sW4 = (const float4*)sW;
    #pragma unroll
    for (int i = 0; i < FIN; i++) {
        float xi = xv[i];
        float4 w0 = sW4[(i * HD + o) * 2 + 0];
        float4 w1 = sW4[(i * HD + o) * 2 + 1];
        acc0.x = fmaf(xi, w0.x, acc0.x); acc0.y = fmaf(xi, w0.y, acc0.y);
        acc0.z = fmaf(xi, w0.z, acc0.z); acc0.w = fmaf(xi, w0.w, acc0.w);
        acc1.x = fmaf(xi, w1.x, acc1.x); acc1.y = fmaf(xi, w1.y, acc1.y);
        acc1.z = fmaf(xi, w1.z, acc1.z); acc1.w = fmaf(xi, w1.w, acc1.w);
        bacc = fmaf(xi, sWc[i * HD + o], bacc);
    }

    __half2 hy[4];
    hy[0] = __floats2half2_rn(acc0.x, acc0.y);
    hy[1] = __floats2half2_rn(acc0.z, acc0.w);
    hy[2] = __floats2half2_rn(acc1.x, acc1.y);
    hy[3] = __floats2half2_rn(acc1.z, acc1.w);
    *(uint4*)(g_Yh + n * 32 + o * 4) = *(const uint4*)hy;
    g_base[gid] = bacc;
}

// Edge layer 0: 8 lanes/edge, 4 edges/thread. PDL: ei/ea loads + half2
// packing pre-sync; Y gathers + REDs post-sync. Side product: lane r==0 of
// each edge group stores the packed fp16 ea (16B) to g_eah for layer 1.
__global__ void __launch_bounds__(256, 4)
k_edge0(const int* __restrict__ ei, const float* __restrict__ ea) {
    const int Q = NE / 4;
    int gid = blockIdx.x * blockDim.x + threadIdx.x;
    int r = gid & 7;
    int t = gid >> 3;             // [0, NE/4)
    int e0 = t, e1 = t + Q, e2 = t + 2 * Q, e3 = t + 3 * Q;

    int src0 = __ldg(ei + e0);
    int src1 = __ldg(ei + e1);
    int src2 = __ldg(ei + e2);
    int src3 = __ldg(ei + e3);
    int dst0 = __ldg(ei + NE + e0);
    int dst1 = __ldg(ei + NE + e1);
    int dst2 = __ldg(ei + NE + e2);
    int dst3 = __ldg(ei + NE + e3);
    float4 a00 = __ldg((const float4*)(ea + e0 * FE));
    float4 a01 = __ldg((const float4*)(ea + e0 * FE + 4));
    float4 a10 = __ldg((const float4*)(ea + e1 * FE));
    float4 a11 = __ldg((const float4*)(ea + e1 * FE + 4));
    float4 a20 = __ldg((const float4*)(ea + e2 * FE));
    float4 a21 = __ldg((const float4*)(ea + e2 * FE + 4));
    float4 a30 = __ldg((const float4*)(ea + e3 * FE));
    float4 a31 = __ldg((const float4*)(ea + e3 * FE + 4));

    // pack ea to half2 pre-sync (independent of predecessor output)
    __half2 eh[4][4];
    #define PACK_EA(k, A0, A1)                          \
        eh[k][0] = __floats2half2_rn((A0).x, (A0).y);   \
        eh[k][1] = __floats2half2_rn((A0).z, (A0).w);   \
        eh[k][2] = __floats2half2_rn((A1).x, (A1).y);   \
        eh[k][3] = __floats2half2_rn((A1).z, (A1).w);
    PACK_EA(0, a00, a01) PACK_EA(1, a10, a11)
    PACK_EA(2, a20, a21) PACK_EA(3, a30, a31)
    #undef PACK_EA

    // stash fp16 ea for layer 1 (one lane per edge group; independent of
    // predecessor, so also pre-sync)
    if (r == 0) {
        g_eah[e0] = *(const uint4*)eh[0];
        g_eah[e1] = *(const uint4*)eh[1];
        g_eah[e2] = *(const uint4*)eh[2];
        g_eah[e3] = *(const uint4*)eh[3];
    }

    cudaGridDependencySynchronize();   // wait for k_node1 (g_Yh, agg[0]=0)

    uint4 yq0 = __ldg((const uint4*)(g_Yh + src0 * 32 + r * 4));
    uint4 yq1 = __ldg((const uint4*)(g_Yh + src1 * 32 + r * 4));
    uint4 yq2 = __ldg((const uint4*)(g_Yh + src2 * 32 + r * 4));
    uint4 yq3 = __ldg((const uint4*)(g_Yh + src3 * 32 + r * 4));

    const unsigned FULL = 0xffffffffu;
    int lane = threadIdx.x & 31;
    float* aggL = g_agg[0];

    #define EDGE_EMIT(yq, k, dst)                                               \
    {                                                                           \
        const __half2* yh = (const __half2*)&(yq);                              \
        __half2 hac = __hmul2(eh[k][0], yh[0]);                                 \
        hac = __hfma2(eh[k][1], yh[1], hac);                                    \
        hac = __hfma2(eh[k][2], yh[2], hac);                                    \
        hac = __hfma2(eh[k][3], yh[3], hac);                                    \
        float2 fa = __half22float2(hac);                                        \
        float m = fa.x + fa.y;                                                  \
        float ma = __shfl_sync(FULL, m, (lane + 1) & 31);                       \
        float mb = __shfl_sync(FULL, m, (lane + 2) & 31);                       \
        float mc = __shfl_sync(FULL, m, (lane + 3) & 31);                       \
        if ((r & 3) == 0) {                                                     \
            float* p = aggL + (dst) * HD + r;                                   \
            asm volatile("red.global.add.v4.f32 [%0], {%1, %2, %3, %4};"        \
                         :: "l"(p), "f"(m), "f"(ma), "f"(mb), "f"(mc)           \
                         : "memory");                                           \
        }                                                                       \
    }

    EDGE_EMIT(yq0, 0, dst0)
    EDGE_EMIT(yq1, 1, dst1)
    EDGE_EMIT(yq2, 2, dst2)
    EDGE_EMIT(yq3, 3, dst3)
    #undef EDGE_EMIT
}

// h1 = relu(agg1 + base1); layer-2 per-node precompute (thread per (n,o)).
// PDL: smem weight staging + agg[1] zeroing run pre-sync.
__global__ void k_node2(const float* __restrict__ We2, const float* __restrict__ be2,
                        const float* __restrict__ root2, const float* __restrict__ b2) {
    __shared__ float sW[HD * HD * HD];    // [i][o][a]
    __shared__ float sWc[HD * HD];        // root2 + be2 : [i][o]
    for (int t = threadIdx.x; t < HD * 64; t += blockDim.x) {
        int i = t >> 6, o = (t >> 3) & 7, a = t & 7;
        sW[t] = We2[a * (HD * HD) + i * HD + o];
    }
    for (int t = threadIdx.x; t < HD * HD; t += blockDim.x)
        sWc[t] = root2[t] + be2[t];

    int gid = blockIdx.x * blockDim.x + threadIdx.x;
    if (gid < NN * 2)
        ((float4*)g_agg[1])[gid] = make_float4(0.f, 0.f, 0.f, 0.f);
    __syncthreads();

    cudaGridDependencySynchronize();   // wait for k_edge0 REDs

    int n = gid >> 3, o = gid & 7;
    if (n >= NN) return;

    float h[HD];
    {
        const float4* ap = (const float4*)(g_agg[0] + n * HD);
        const float4* cp = (const float4*)(g_base + n * HD);
        float4 a0 = ap[0], a1 = ap[1], c0 = cp[0], c1 = cp[1];
        h[0] = fmaxf(a0.x + c0.x, 0.f); h[1] = fmaxf(a0.y + c0.y, 0.f);
        h[2] = fmaxf(a0.z + c0.z, 0.f); h[3] = fmaxf(a0.w + c0.w, 0.f);
        h[4] = fmaxf(a1.x + c1.x, 0.f); h[5] = fmaxf(a1.y + c1.y, 0.f);
        h[6] = fmaxf(a1.z + c1.z, 0.f); h[7] = fmaxf(a1.w + c1.w, 0.f);
    }
    __syncwarp();   // all reads of g_base[n][*] done before warp-mates overwrite

    float4 acc0 = make_float4(0.f, 0.f, 0.f, 0.f);
    float4 acc1 = make_float4(0.f, 0.f, 0.f, 0.f);
    float bacc = __ldg(b2 + o);
    const float4* sW4 = (const float4*)sW;
    #pragma unroll
    for (int i = 0; i < HD; i++) {
        float hi = h[i];
        float4 w0 = sW4[(i * HD + o) * 2 + 0];
        float4 w1 = sW4[(i * HD + o) * 2 + 1];
        acc0.x = fmaf(hi, w0.x, acc0.x); acc0.y = fmaf(hi, w0.y, acc0.y);
        acc0.z = fmaf(hi, w0.z, acc0.z); acc0.w = fmaf(hi, w0.w, acc0.w);
        acc1.x = fmaf(hi, w1.x, acc1.x); acc1.y = fmaf(hi, w1.y, acc1.y);
        acc1.z = fmaf(hi, w1.z, acc1.z); acc1.w = fmaf(hi, w1.w, acc1.w);
        bacc = fmaf(hi, sWc[i * HD + o], bacc);
    }

    __half2 hy[4];
    hy[0] = __floats2half2_rn(acc0.x, acc0.y);
    hy[1] = __floats2half2_rn(acc0.z, acc0.w);
    hy[2] = __floats2half2_rn(acc1.x, acc1.y);
    hy[3] = __floats2half2_rn(acc1.z, acc1.w);
    *(uint4*)(g_Yh + n * 32 + o * 4) = *(const uint4*)hy;
    g_base[gid] = bacc;
}

// Edge layer 1: lean variant — ea comes from g_eah as ONE 16B load (half
// the ea bytes of layer 0, zero pack instructions) -> fewer regs, 5
// blocks/SM resident. PDL: ei loads pre-sync; eah/Y post-sync (eah written
// by k_edge0, Y by k_node2).
__global__ void __launch_bounds__(256, 5)
k_edge1(const int* __restrict__ ei) {
    const int Q = NE / 4;
    int gid = blockIdx.x * blockDim.x + threadIdx.x;
    int r = gid & 7;
    int t = gid >> 3;             // [0, NE/4)
    int e0 = t, e1 = t + Q, e2 = t + 2 * Q, e3 = t + 3 * Q;

    int src0 = __ldg(ei + e0);
    int src1 = __ldg(ei + e1);
    int src2 = __ldg(ei + e2);
    int src3 = __ldg(ei + e3);
    int dst0 = __ldg(ei + NE + e0);
    int dst1 = __ldg(ei + NE + e1);
    int dst2 = __ldg(ei + NE + e2);
    int dst3 = __ldg(ei + NE + e3);

    cudaGridDependencySynchronize();   // wait for k_node2 (g_Yh, agg[1]=0)

    uint4 eq0 = __ldg(g_eah + e0);
    uint4 eq1 = __ldg(g_eah + e1);
    uint4 eq2 = __ldg(g_eah + e2);
    uint4 eq3 = __ldg(g_eah + e3);
    uint4 yq0 = __ldg((const uint4*)(g_Yh + src0 * 32 + r * 4));
    uint4 yq1 = __ldg((const uint4*)(g_Yh + src1 * 32 + r * 4));
    uint4 yq2 = __ldg((const uint4*)(g_Yh + src2 * 32 + r * 4));
    uint4 yq3 = __ldg((const uint4*)(g_Yh + src3 * 32 + r * 4));

    const unsigned FULL = 0xffffffffu;
    int lane = threadIdx.x & 31;
    float* aggL = g_agg[1];

    #define EDGE_EMIT(yq, eq, dst)                                              \
    {                                                                           \
        const __half2* yh = (const __half2*)&(yq);                              \
        const __half2* ehp = (const __half2*)&(eq);                             \
        __half2 hac = __hmul2(ehp[0], yh[0]);                                   \
        hac = __hfma2(ehp[1], yh[1], hac);                                      \
        hac = __hfma2(ehp[2], yh[2], hac);                                      \
        hac = __hfma2(ehp[3], yh[3], hac);                                      \
        float2 fa = __half22float2(hac);                                        \
        float m = fa.x + fa.y;                                                  \
        float ma = __shfl_sync(FULL, m, (lane + 1) & 31);                       \
        float mb = __shfl_sync(FULL, m, (lane + 2) & 31);                       \
        float mc = __shfl_sync(FULL, m, (lane + 3) & 31);                       \
        if ((r & 3) == 0) {                                                     \
            float* p = aggL + (dst) * HD + r;                                   \
            asm volatile("red.global.add.v4.f32 [%0], {%1, %2, %3, %4};"        \
                         :: "l"(p), "f"(m), "f"(ma), "f"(mb), "f"(mc)           \
                         : "memory");                                           \
        }                                                                       \
    }

    EDGE_EMIT(yq0, eq0, dst0)
    EDGE_EMIT(yq1, eq1, dst1)
    EDGE_EMIT(yq2, eq2, dst2)
    EDGE_EMIT(yq3, eq3, dst3)
    #undef EDGE_EMIT
}

// h2 = relu(agg2 + base2); out[batch[n]] += sum_o h2[o]*Wlast[o].
// batch SORTED -> warp-segmented reduction; batch/Wlast loads pre-sync.
__global__ void k_pool(const int* __restrict__ batch, const float* __restrict__ Wlast,
                       float* __restrict__ out) {
    int n = blockIdx.x * blockDim.x + threadIdx.x;
    int lane = threadIdx.x & 31;
    int bid = -1;
    if (n < NN) bid = __ldg(batch + n);
    float w0 = __ldg(Wlast + 0), w1 = __ldg(Wlast + 1);
    float w2 = __ldg(Wlast + 2), w3 = __ldg(Wlast + 3);
    float w4 = __ldg(Wlast + 4), w5 = __ldg(Wlast + 5);
    float w6 = __ldg(Wlast + 6), w7 = __ldg(Wlast + 7);

    cudaGridDependencySynchronize();   // wait for k_edge1 REDs

    float s = 0.f;
    if (n < NN) {
        const float4* ap = (const float4*)(g_agg[1] + n * HD);
        const float4* cp = (const float4*)(g_base + n * HD);
        float4 a0 = ap[0], a1 = ap[1], c0 = cp[0], c1 = cp[1];
        s = fmaxf(a0.x + c0.x, 0.f) * w0 + fmaxf(a0.y + c0.y, 0.f) * w1
          + fmaxf(a0.z + c0.z, 0.f) * w2 + fmaxf(a0.w + c0.w, 0.f) * w3
          + fmaxf(a1.x + c1.x, 0.f) * w4 + fmaxf(a1.y + c1.y, 0.f) * w5
          + fmaxf(a1.z + c1.z, 0.f) * w6 + fmaxf(a1.w + c1.w, 0.f) * w7;
    }
    const unsigned FULL = 0xffffffffu;
    int bprev = __shfl_up_sync(FULL, bid, 1);
    #pragma unroll
    for (int d = 1; d < 32; d <<= 1) {
        float tv = __shfl_down_sync(FULL, s, d);
        int  tb = __shfl_down_sync(FULL, bid, d);
        if (lane + d < 32 && tb == bid) s += tv;
    }
    bool leader = (n < NN) && (lane == 0 || bprev != bid);
    if (leader) atomicAdd(out + bid, s);
}

template <typename F, typename... Args>
static void launch_pdl(F f, int grid, int block, Args... args) {
    cudaLaunchConfig_t cfg = {};
    cfg.gridDim = dim3(grid, 1, 1);
    cfg.blockDim = dim3(block, 1, 1);
    cfg.dynamicSmemBytes = 0;
    cfg.stream = 0;
    cudaLaunchAttribute at[1];
    at[0].id = cudaLaunchAttributeProgrammaticStreamSerialization;
    at[0].val.programmaticStreamSerializationAllowed = 1;
    cfg.attrs = at;
    cfg.numAttrs = 1;
    cudaLaunchKernelEx(&cfg, f, args...);
}

extern "C" void kernel_launch(void* const* d_in, const int* in_sizes, int n_in,
                              void* d_out, int out_size) {
    const float* x     = (const float*)d_in[0];
    const int*   ei    = (const int*)  d_in[1];
    const float* ea    = (const float*)d_in[2];
    const int*   batch = (const int*)  d_in[3];
    const float* We1   = (const float*)d_in[4];
    const float* be1   = (const float*)d_in[5];
    const float* root1 = (const float*)d_in[6];
    const float* b1    = (const float*)d_in[7];
    const float* We2   = (const float*)d_in[8];
    const float* be2   = (const float*)d_in[9];
    const float* root2 = (const float*)d_in[10];
    const float* b2    = (const float*)d_in[11];
    const float* Wlast = (const float*)d_in[12];
    const float* blast = (const float*)d_in[13];
    float* out = (float*)d_out;

    k_node1<<<(NN * HD + 255) / 256, 256>>>(x, We1, be1, root1, b1, blast, out);
    launch_pdl(k_edge0, (NE / 4) * 8 / 256, 256, ei, ea);
    launch_pdl(k_node2, (NN * HD + 255) / 256, 256, We2, be2, root2, b2);
    launch_pdl(k_edge1, (NE / 4) * 8 / 256, 256, ei);
    launch_pdl(k_pool,  (NN + 255) / 256, 256, batch, Wlast, out);
}

// round 16
// speedup vs baseline: 1.2017x; 1.0644x over previous
#include <cuda_runtime.h>
#include <cuda_fp16.h>

#define NN 50000
#define NE 800000
#define FIN 16
#define FE 8
#define HD 8
#define NG 512

// Scratch (allocation-free: __device__ globals).
// g_Yh:  per-node factor table fp16 [n][o][a]: row = 128B = 1 line; lane r's
//        uint4 at n*128+r*16 covers o=r fully (in-lane dot).
// g_eah: edge_attr as fp16 (8 halves = 16B per edge), written by edge layer 0
//        as a side product (it already packs ea to half2 for its own dot).
// g_base: per-node base term base[n][o], fp32.
// g_agg:  scatter accumulators fp32, [layer][n*8+o].
__device__ __half2 g_Yh[NN * 32];
__device__ uint4   g_eah[NE];
__device__ float   g_base[NN * HD];
__device__ float   g_agg[2][NN * HD];

// Layer-1 per-node precompute, thread per (n,o). Zeroes agg[0], seeds out.
__global__ void k_node1(const float* __restrict__ x, const float* __restrict__ We1,
                        const float* __restrict__ be1, const float* __restrict__ root1,
                        const float* __restrict__ b1, const float* __restrict__ blast,
                        float* __restrict__ out) {
    __shared__ float sW[FIN * HD * HD];   // [i][o][a]
    __shared__ float sWc[FIN * HD];       // root1 + be1 : [i][o]
    for (int t = threadIdx.x; t < FIN * 64; t += blockDim.x) {
        int i = t >> 6, o = (t >> 3) & 7, a = t & 7;
        sW[t] = We1[a * (FIN * HD) + i * HD + o];
    }
    for (int t = threadIdx.x; t < FIN * HD; t += blockDim.x)
        sWc[t] = root1[t] + be1[t];
    __syncthreads();

    int gid = blockIdx.x * blockDim.x + threadIdx.x;
    if (gid < NG) out[gid] = blast[0];
    if (gid < NN * 2)
        ((float4*)g_agg[0])[gid] = make_float4(0.f, 0.f, 0.f, 0.f);
    int n = gid >> 3, o = gid & 7;
    if (n >= NN) return;

    float xv[FIN];
    const float4* xp = (const float4*)(x + n * FIN);
    #pragma unroll
    for (int q = 0; q < 4; q++) {
        float4 v = xp[q];
        xv[q * 4 + 0] = v.x; xv[q * 4 + 1] = v.y;
        xv[q * 4 + 2] = v.z; xv[q * 4 + 3] = v.w;
    }

    float4 acc0 = make_float4(0.f, 0.f, 0.f, 0.f);   // a = 0..3
    float4 acc1 = make_float4(0.f, 0.f, 0.f, 0.f);   // a = 4..7
    float bacc = __ldg(b1 + o);
    const float4* sW4 = (const float4*)sW;
    #pragma unroll
    for (int i = 0; i < FIN; i++) {
        float xi = xv[i];
        float4 w0 = sW4[(i * HD + o) * 2 + 0];
        float4 w1 = sW4[(i * HD + o) * 2 + 1];
        acc0.x = fmaf(xi, w0.x, acc0.x); acc0.y = fmaf(xi, w0.y, acc0.y);
        acc0.z = fmaf(xi, w0.z, acc0.z); acc0.w = fmaf(xi, w0.w, acc0.w);
        acc1.x = fmaf(xi, w1.x, acc1.x); acc1.y = fmaf(xi, w1.y, acc1.y);
        acc1.z = fmaf(xi, w1.z, acc1.z); acc1.w = fmaf(xi, w1.w, acc1.w);
        bacc = fmaf(xi, sWc[i * HD + o], bacc);
    }

    __half2 hy[4];
    hy[0] = __floats2half2_rn(acc0.x, acc0.y);
    hy[1] = __floats2half2_rn(acc0.z, acc0.w);
    hy[2] = __floats2half2_rn(acc1.x, acc1.y);
    hy[3] = __floats2half2_rn(acc1.z, acc1.w);
    *(uint4*)(g_Yh + n * 32 + o * 4) = *(const uint4*)hy;
    g_base[gid] = bacc;
}

// Edge layer 0: 8 lanes/edge, 4 edges/thread. PDL: ei/ea loads + half2
// packing pre-sync; Y gathers + REDs post-sync. Side product: lane r==0 of
// each edge group stores the packed fp16 ea (16B) to g_eah for layer 1.
// Scatter: each lane issues ONE scalar red.f32 per edge for its own o=r —
// no shuffles (REDG spread = 0.854 cyc/lane; all 8 lanes hit one 32B slot
// = one line, same wavefronts as red.v4 but 16 fewer instrs/thread).
__global__ void __launch_bounds__(256, 5)
k_edge0(const int* __restrict__ ei, const float* __restrict__ ea) {
    const int Q = NE / 4;
    int gid = blockIdx.x * blockDim.x + threadIdx.x;
    int r = gid & 7;
    int t = gid >> 3;             // [0, NE/4)
    int e0 = t, e1 = t + Q, e2 = t + 2 * Q, e3 = t + 3 * Q;

    int src0 = __ldg(ei + e0);
    int src1 = __ldg(ei + e1);
    int src2 = __ldg(ei + e2);
    int src3 = __ldg(ei + e3);
    int dst0 = __ldg(ei + NE + e0);
    int dst1 = __ldg(ei + NE + e1);
    int dst2 = __ldg(ei + NE + e2);
    int dst3 = __ldg(ei + NE + e3);
    float4 a00 = __ldg((const float4*)(ea + e0 * FE));
    float4 a01 = __ldg((const float4*)(ea + e0 * FE + 4));
    float4 a10 = __ldg((const float4*)(ea + e1 * FE));
    float4 a11 = __ldg((const float4*)(ea + e1 * FE + 4));
    float4 a20 = __ldg((const float4*)(ea + e2 * FE));
    float4 a21 = __ldg((const float4*)(ea + e2 * FE + 4));
    float4 a30 = __ldg((const float4*)(ea + e3 * FE));
    float4 a31 = __ldg((const float4*)(ea + e3 * FE + 4));

    // pack ea to half2 pre-sync (independent of predecessor output)
    __half2 eh[4][4];
    #define PACK_EA(k, A0, A1)                          \
        eh[k][0] = __floats2half2_rn((A0).x, (A0).y);   \
        eh[k][1] = __floats2half2_rn((A0).z, (A0).w);   \
        eh[k][2] = __floats2half2_rn((A1).x, (A1).y);   \
        eh[k][3] = __floats2half2_rn((A1).z, (A1).w);
    PACK_EA(0, a00, a01) PACK_EA(1, a10, a11)
    PACK_EA(2, a20, a21) PACK_EA(3, a30, a31)
    #undef PACK_EA

    // stash fp16 ea for layer 1 (one lane per edge group; pre-sync)
    if (r == 0) {
        g_eah[e0] = *(const uint4*)eh[0];
        g_eah[e1] = *(const uint4*)eh[1];
        g_eah[e2] = *(const uint4*)eh[2];
        g_eah[e3] = *(const uint4*)eh[3];
    }

    cudaGridDependencySynchronize();   // wait for k_node1 (g_Yh, agg[0]=0)

    uint4 yq0 = __ldg((const uint4*)(g_Yh + src0 * 32 + r * 4));
    uint4 yq1 = __ldg((const uint4*)(g_Yh + src1 * 32 + r * 4));
    uint4 yq2 = __ldg((const uint4*)(g_Yh + src2 * 32 + r * 4));
    uint4 yq3 = __ldg((const uint4*)(g_Yh + src3 * 32 + r * 4));

    float* aggL = g_agg[0];

    #define EDGE_EMIT(yq, k, dst)                                               \
    {                                                                           \
        const __half2* yh = (const __half2*)&(yq);                              \
        __half2 hac = __hmul2(eh[k][0], yh[0]);                                 \
        hac = __hfma2(eh[k][1], yh[1], hac);                                    \
        hac = __hfma2(eh[k][2], yh[2], hac);                                    \
        hac = __hfma2(eh[k][3], yh[3], hac);                                    \
        float2 fa = __half22float2(hac);                                        \
        float m = fa.x + fa.y;                                                  \
        float* p = aggL + (dst) * HD + r;                                       \
        asm volatile("red.global.add.f32 [%0], %1;"                             \
                     :: "l"(p), "f"(m) : "memory");                             \
    }

    EDGE_EMIT(yq0, 0, dst0)
    EDGE_EMIT(yq1, 1, dst1)
    EDGE_EMIT(yq2, 2, dst2)
    EDGE_EMIT(yq3, 3, dst3)
    #undef EDGE_EMIT
}

// h1 = relu(agg1 + base1); layer-2 per-node precompute (thread per (n,o)).
// PDL: smem weight staging + agg[1] zeroing run pre-sync.
__global__ void k_node2(const float* __restrict__ We2, const float* __restrict__ be2,
                        const float* __restrict__ root2, const float* __restrict__ b2) {
    __shared__ float sW[HD * HD * HD];    // [i][o][a]
    __shared__ float sWc[HD * HD];        // root2 + be2 : [i][o]
    for (int t = threadIdx.x; t < HD * 64; t += blockDim.x) {
        int i = t >> 6, o = (t >> 3) & 7, a = t & 7;
        sW[t] = We2[a * (HD * HD) + i * HD + o];
    }
    for (int t = threadIdx.x; t < HD * HD; t += blockDim.x)
        sWc[t] = root2[t] + be2[t];

    int gid = blockIdx.x * blockDim.x + threadIdx.x;
    if (gid < NN * 2)
        ((float4*)g_agg[1])[gid] = make_float4(0.f, 0.f, 0.f, 0.f);
    __syncthreads();

    cudaGridDependencySynchronize();   // wait for k_edge0 REDs

    int n = gid >> 3, o = gid & 7;
    if (n >= NN) return;

    float h[HD];
    {
        const float4* ap = (const float4*)(g_agg[0] + n * HD);
        const float4* cp = (const float4*)(g_base + n * HD);
        float4 a0 = ap[0], a1 = ap[1], c0 = cp[0], c1 = cp[1];
        h[0] = fmaxf(a0.x + c0.x, 0.f); h[1] = fmaxf(a0.y + c0.y, 0.f);
        h[2] = fmaxf(a0.z + c0.z, 0.f); h[3] = fmaxf(a0.w + c0.w, 0.f);
        h[4] = fmaxf(a1.x + c1.x, 0.f); h[5] = fmaxf(a1.y + c1.y, 0.f);
        h[6] = fmaxf(a1.z + c1.z, 0.f); h[7] = fmaxf(a1.w + c1.w, 0.f);
    }
    __syncwarp();   // all reads of g_base[n][*] done before warp-mates overwrite

    float4 acc0 = make_float4(0.f, 0.f, 0.f, 0.f);
    float4 acc1 = make_float4(0.f, 0.f, 0.f, 0.f);
    float bacc = __ldg(b2 + o);
    const float4* sW4 = (const float4*)sW;
    #pragma unroll
    for (int i = 0; i < HD; i++) {
        float hi = h[i];
        float4 w0 = sW4[(i * HD + o) * 2 + 0];
        float4 w1 = sW4[(i * HD + o) * 2 + 1];
        acc0.x = fmaf(hi, w0.x, acc0.x); acc0.y = fmaf(hi, w0.y, acc0.y);
        acc0.z = fmaf(hi, w0.z, acc0.z); acc0.w = fmaf(hi, w0.w, acc0.w);
        acc1.x = fmaf(hi, w1.x, acc1.x); acc1.y = fmaf(hi, w1.y, acc1.y);
        acc1.z = fmaf(hi, w1.z, acc1.z); acc1.w = fmaf(hi, w1.w, acc1.w);
        bacc = fmaf(hi, sWc[i * HD + o], bacc);
    }

    __half2 hy[4];
    hy[0] = __floats2half2_rn(acc0.x, acc0.y);
    hy[1] = __floats2half2_rn(acc0.z, acc0.w);
    hy[2] = __floats2half2_rn(acc1.x, acc1.y);
    hy[3] = __floats2half2_rn(acc1.z, acc1.w);
    *(uint4*)(g_Yh + n * 32 + o * 4) = *(const uint4*)hy;
    g_base[gid] = bacc;
}

// Edge layer 1: lean variant — ea from g_eah as ONE 16B load, scalar REDs,
// no shuffles. PDL: ei loads pre-sync; eah/Y post-sync.
__global__ void __launch_bounds__(256, 5)
k_edge1(const int* __restrict__ ei) {
    const int Q = NE / 4;
    int gid = blockIdx.x * blockDim.x + threadIdx.x;
    int r = gid & 7;
    int t = gid >> 3;             // [0, NE/4)
    int e0 = t, e1 = t + Q, e2 = t + 2 * Q, e3 = t + 3 * Q;

    int src0 = __ldg(ei + e0);
    int src1 = __ldg(ei + e1);
    int src2 = __ldg(ei + e2);
    int src3 = __ldg(ei + e3);
    int dst0 = __ldg(ei + NE + e0);
    int dst1 = __ldg(ei + NE + e1);
    int dst2 = __ldg(ei + NE + e2);
    int dst3 = __ldg(ei + NE + e3);

    cudaGridDependencySynchronize();   // wait for k_node2 (g_Yh, agg[1]=0)

    uint4 eq0 = __ldg(g_eah + e0);
    uint4 eq1 = __ldg(g_eah + e1);
    uint4 eq2 = __ldg(g_eah + e2);
    uint4 eq3 = __ldg(g_eah + e3);
    uint4 yq0 = __ldg((const uint4*)(g_Yh + src0 * 32 + r * 4));
    uint4 yq1 = __ldg((const uint4*)(g_Yh + src1 * 32 + r * 4));
    uint4 yq2 = __ldg((const uint4*)(g_Yh + src2 * 32 + r * 4));
    uint4 yq3 = __ldg((const uint4*)(g_Yh + src3 * 32 + r * 4));

    float* aggL = g_agg[1];

    #define EDGE_EMIT(yq, eq, dst)                                              \
    {                                                                           \
        const __half2* yh = (const __half2*)&(yq);                              \
        const __half2* ehp = (const __half2*)&(eq);                             \
        __half2 hac = __hmul2(ehp[0], yh[0]);                                   \
        hac = __hfma2(ehp[1], yh[1], hac);                                      \
        hac = __hfma2(ehp[2], yh[2], hac);                                      \
        hac = __hfma2(ehp[3], yh[3], hac);                                      \
        float2 fa = __half22float2(hac);                                        \
        float m = fa.x + fa.y;                                                  \
        float* p = aggL + (dst) * HD + r;                                       \
        asm volatile("red.global.add.f32 [%0], %1;"                             \
                     :: "l"(p), "f"(m) : "memory");                             \
    }

    EDGE_EMIT(yq0, eq0, dst0)
    EDGE_EMIT(yq1, eq1, dst1)
    EDGE_EMIT(yq2, eq2, dst2)
    EDGE_EMIT(yq3, eq3, dst3)
    #undef EDGE_EMIT
}

// h2 = relu(agg2 + base2); out[batch[n]] += sum_o h2[o]*Wlast[o].
// batch SORTED -> warp-segmented reduction; batch/Wlast loads pre-sync.
__global__ void k_pool(const int* __restrict__ batch, const float* __restrict__ Wlast,
                       float* __restrict__ out) {
    int n = blockIdx.x * blockDim.x + threadIdx.x;
    int lane = threadIdx.x & 31;
    int bid = -1;
    if (n < NN) bid = __ldg(batch + n);
    float w0 = __ldg(Wlast + 0), w1 = __ldg(Wlast + 1);
    float w2 = __ldg(Wlast + 2), w3 = __ldg(Wlast + 3);
    float w4 = __ldg(Wlast + 4), w5 = __ldg(Wlast + 5);
    float w6 = __ldg(Wlast + 6), w7 = __ldg(Wlast + 7);

    cudaGridDependencySynchronize();   // wait for k_edge1 REDs

    float s = 0.f;
    if (n < NN) {
        const float4* ap = (const float4*)(g_agg[1] + n * HD);
        const float4* cp = (const float4*)(g_base + n * HD);
        float4 a0 = ap[0], a1 = ap[1], c0 = cp[0], c1 = cp[1];
        s = fmaxf(a0.x + c0.x, 0.f) * w0 + fmaxf(a0.y + c0.y, 0.f) * w1
          + fmaxf(a0.z + c0.z, 0.f) * w2 + fmaxf(a0.w + c0.w, 0.f) * w3
          + fmaxf(a1.x + c1.x, 0.f) * w4 + fmaxf(a1.y + c1.y, 0.f) * w5
          + fmaxf(a1.z + c1.z, 0.f) * w6 + fmaxf(a1.w + c1.w, 0.f) * w7;
    }
    const unsigned FULL = 0xffffffffu;
    int bprev = __shfl_up_sync(FULL, bid, 1);
    #pragma unroll
    for (int d = 1; d < 32; d <<= 1) {
        float tv = __shfl_down_sync(FULL, s, d);
        int  tb = __shfl_down_sync(FULL, bid, d);
        if (lane + d < 32 && tb == bid) s += tv;
    }
    bool leader = (n < NN) && (lane == 0 || bprev != bid);
    if (leader) atomicAdd(out + bid, s);
}

template <typename F, typename... Args>
static void launch_pdl(F f, int grid, int block, Args... args) {
    cudaLaunchConfig_t cfg = {};
    cfg.gridDim = dim3(grid, 1, 1);
    cfg.blockDim = dim3(block, 1, 1);
    cfg.dynamicSmemBytes = 0;
    cfg.stream = 0;
    cudaLaunchAttribute at[1];
    at[0].id = cudaLaunchAttributeProgrammaticStreamSerialization;
    at[0].val.programmaticStreamSerializationAllowed = 1;
    cfg.attrs = at;
    cfg.numAttrs = 1;
    cudaLaunchKernelEx(&cfg, f, args...);
}

extern "C" void kernel_launch(void* const* d_in, const int* in_sizes, int n_in,
                              void* d_out, int out_size) {
    const float* x     = (const float*)d_in[0];
    const int*   ei    = (const int*)  d_in[1];
    const float* ea    = (const float*)d_in[2];
    const int*   batch = (const int*)  d_in[3];
    const float* We1   = (const float*)d_in[4];
    const float* be1   = (const float*)d_in[5];
    const float* root1 = (const float*)d_in[6];
    const float* b1    = (const float*)d_in[7];
    const float* We2   = (const float*)d_in[8];
    const float* be2   = (const float*)d_in[9];
    const float* root2 = (const float*)d_in[10];
    const float* b2    = (const float*)d_in[11];
    const float* Wlast = (const float*)d_in[12];
    const float* blast = (const float*)d_in[13];
    float* out = (float*)d_out;

    k_node1<<<(NN * HD + 255) / 256, 256>>>(x, We1, be1, root1, b1, blast, out);
    launch_pdl(k_edge0, (NE / 4) * 8 / 256, 256, ei, ea);
    launch_pdl(k_node2, (NN * HD + 255) / 256, 256, We2, be2, root2, b2);
    launch_pdl(k_edge1, (NE / 4) * 8 / 256, 256, ei);
    launch_pdl(k_pool,  (NN + 255) / 256, 256, batch, Wlast, out);
}